// round 12
// baseline (speedup 1.0000x reference)
#include <cuda_runtime.h>
#include <cuda_fp16.h>
#include <cstdint>

// Problem constants
#define NN   4096
#define INF  256
#define Hh   4
#define Dd   64
#define HD   256         // Hh*Dd
#define TIA  32          // i-rows per CTA in aggregation
#define JC   64          // j-chunk
#define JSPLIT 2
#define JPER (NN/JSPLIT) // 2048
#define NCHUNK (JPER/JC) // 32

using u64 = unsigned long long;
using u32 = unsigned int;

// ---------------- device scratch ---------------------------------------------
__device__ float  g_h [NN*HD];            // fp32 h = x@W (for scores)
__device__ __half g_hh[NN*HD];            // fp16 copy (MMA B operand)
__device__ float g_si[NN*Hh];
__device__ float g_sj[NN*Hh];
__device__ float g_eip[NN*Hh];            // exp(si-2)
__device__ float g_ein[NN*Hh];            // exp(0.2*si-2)
__device__ float g_ejp[NN*Hh];            // exp(sj-2)
__device__ float g_ejn[NN*Hh];            // exp(0.2*sj-2)
// SoA tables per 64-j chunk: [chunk][h][comp(sj,ejp,ejn)][jp 0..31] u32(half2)
__device__ u32   g_tab2[(NN/64)*384];
__device__ float g_part[JSPLIT*NN*HD];    // partial accumulators
__device__ float g_Z[JSPLIT*NN*Hh];       // partial normalizers

// ---------------- packed helpers ----------------------------------------------
__device__ __forceinline__ u64 pack2(float x, float y) {
    u64 r; asm("mov.b64 %0, {%1,%2};" : "=l"(r) : "f"(x), "f"(y)); return r;
}
__device__ __forceinline__ float2 unpack2(u64 v) {
    float2 r; asm("mov.b64 {%0,%1}, %2;" : "=f"(r.x), "=f"(r.y) : "l"(v)); return r;
}
__device__ __forceinline__ u64 fma2(u64 a, u64 b, u64 c) {
    u64 d; asm("fma.rn.f32x2 %0, %1, %2, %3;" : "=l"(d) : "l"(a), "l"(b), "l"(c));
    return d;
}
__device__ __forceinline__ u32 h2_u32(__half2 v) {
    __half2_raw r = *(__half2_raw*)&v;
    return (u32)r.x | ((u32)r.y << 16);
}
__device__ __forceinline__ __half2 u32_h2(u32 v) {
    __half2_raw r; r.x = (unsigned short)(v & 0xFFFFu); r.y = (unsigned short)(v >> 16);
    return *(__half2*)&r;
}

// ---------------- smem ld/st helpers ------------------------------------------
__device__ __forceinline__ int4 lds128(u32 a) {
    int4 v; asm volatile("ld.shared.v4.u32 {%0,%1,%2,%3}, [%4];"
        : "=r"(v.x), "=r"(v.y), "=r"(v.z), "=r"(v.w) : "r"(a));
    return v;
}
__device__ __forceinline__ void sts128(u32 a, u32 x, u32 y, u32 z, u32 w) {
    asm volatile("st.shared.v4.u32 [%0], {%1,%2,%3,%4};"
        :: "r"(a), "r"(x), "r"(y), "r"(z), "r"(w));
}

// ---------------- cp.async helpers ---------------------------------------------
__device__ __forceinline__ void cp_async16(u32 dst, const void* src) {
    asm volatile("cp.async.cg.shared.global [%0], [%1], 16;" :: "r"(dst), "l"(src));
}
__device__ __forceinline__ void cp_commit() { asm volatile("cp.async.commit_group;"); }
__device__ __forceinline__ void cp_wait0()  {
    asm volatile("cp.async.wait_group 0;" ::: "memory");
}

// ---------------- mma / ldmatrix helpers --------------------------------------
__device__ __forceinline__ void ldsm_x4(u32& r0, u32& r1, u32& r2, u32& r3, u32 addr) {
    asm volatile("ldmatrix.sync.aligned.m8n8.x4.shared.b16 {%0,%1,%2,%3}, [%4];"
                 : "=r"(r0), "=r"(r1), "=r"(r2), "=r"(r3) : "r"(addr));
}
__device__ __forceinline__ void ldsm_x4_t(u32& r0, u32& r1, u32& r2, u32& r3, u32 addr) {
    asm volatile("ldmatrix.sync.aligned.m8n8.x4.trans.shared.b16 {%0,%1,%2,%3}, [%4];"
                 : "=r"(r0), "=r"(r1), "=r"(r2), "=r"(r3) : "r"(addr));
}
__device__ __forceinline__ void ldsm_x2_t(u32& r0, u32& r1, u32 addr) {
    asm volatile("ldmatrix.sync.aligned.m8n8.x2.trans.shared.b16 {%0,%1}, [%2];"
                 : "=r"(r0), "=r"(r1) : "r"(addr));
}
__device__ __forceinline__ void mma16816(float* c, u32 a0, u32 a1, u32 a2, u32 a3,
                                         u32 b0, u32 b1) {
    asm volatile("mma.sync.aligned.m16n8k16.row.col.f32.f16.f16.f32 "
                 "{%0,%1,%2,%3},{%4,%5,%6,%7},{%8,%9},{%0,%1,%2,%3};"
                 : "+f"(c[0]), "+f"(c[1]), "+f"(c[2]), "+f"(c[3])
                 : "r"(a0), "r"(a1), "r"(a2), "r"(a3), "r"(b0), "r"(b1));
}

// ---------------- kernel 1: h = x @ W  (also writes fp16 copy) ----------------
__global__ void __launch_bounds__(256) gemm_xw(const float* __restrict__ x,
                                               const float* __restrict__ W) {
    __shared__ float As[16*64];   // [k][m]
    __shared__ float Bs[16*64];   // [k][n]
    const int t = threadIdx.x;
    const int row0 = blockIdx.y * 64;
    const int col0 = blockIdx.x * 64;
    const int tx = t & 15;
    const int ty = t >> 4;

    u64 acc[2][4];
    #pragma unroll
    for (int m = 0; m < 2; m++)
        #pragma unroll
        for (int n = 0; n < 4; n++) acc[m][n] = 0ull;

    for (int kb = 0; kb < INF; kb += 16) {
        {
            const int aRow = t >> 2;
            const int aK4  = (t & 3) * 4;
            float4 av = *(const float4*)(x + (size_t)(row0 + aRow) * INF + kb + aK4);
            As[(aK4 + 0) * 64 + aRow] = av.x;
            As[(aK4 + 1) * 64 + aRow] = av.y;
            As[(aK4 + 2) * 64 + aRow] = av.z;
            As[(aK4 + 3) * 64 + aRow] = av.w;
        }
        {
            const int bK  = t >> 4;
            const int bN4 = (t & 15) * 4;
            *(float4*)&Bs[bK * 64 + bN4] =
                *(const float4*)(W + (size_t)(kb + bK) * HD + col0 + bN4);
        }
        __syncthreads();
        #pragma unroll
        for (int k = 0; k < 16; k++) {
            float4 a4 = *(const float4*)&As[k * 64 + ty * 4];
            float4 b4 = *(const float4*)&Bs[k * 64 + tx * 4];
            u64 a01 = pack2(a4.x, a4.y);
            u64 a23 = pack2(a4.z, a4.w);
            u64 bb0 = pack2(b4.x, b4.x), bb1 = pack2(b4.y, b4.y);
            u64 bb2 = pack2(b4.z, b4.z), bb3 = pack2(b4.w, b4.w);
            acc[0][0] = fma2(a01, bb0, acc[0][0]); acc[1][0] = fma2(a23, bb0, acc[1][0]);
            acc[0][1] = fma2(a01, bb1, acc[0][1]); acc[1][1] = fma2(a23, bb1, acc[1][1]);
            acc[0][2] = fma2(a01, bb2, acc[0][2]); acc[1][2] = fma2(a23, bb2, acc[1][2]);
            acc[0][3] = fma2(a01, bb3, acc[0][3]); acc[1][3] = fma2(a23, bb3, acc[1][3]);
        }
        __syncthreads();
    }
    #pragma unroll
    for (int mp = 0; mp < 2; mp++) {
        float2 v[4];
        #pragma unroll
        for (int n = 0; n < 4; n++) v[n] = unpack2(acc[mp][n]);
        int r0 = row0 + ty * 4 + mp * 2;
        int c0 = col0 + tx * 4;
        #pragma unroll
        for (int n = 0; n < 4; n++) {
            g_h[(size_t)(r0 + 0) * HD + c0 + n] = v[n].x;
            g_h[(size_t)(r0 + 1) * HD + c0 + n] = v[n].y;
        }
        __half2 hx0 = __floats2half2_rn(v[0].x, v[1].x);
        __half2 hx1 = __floats2half2_rn(v[2].x, v[3].x);
        __half2 hy0 = __floats2half2_rn(v[0].y, v[1].y);
        __half2 hy1 = __floats2half2_rn(v[2].y, v[3].y);
        *(__half2*)&g_hh[(size_t)(r0 + 0) * HD + c0]     = hx0;
        *(__half2*)&g_hh[(size_t)(r0 + 0) * HD + c0 + 2] = hx1;
        *(__half2*)&g_hh[(size_t)(r0 + 1) * HD + c0]     = hy0;
        *(__half2*)&g_hh[(size_t)(r0 + 1) * HD + c0 + 2] = hy1;
    }
}

// ---------------- kernel 2: scores + shifted exp tables -----------------------
__global__ void __launch_bounds__(256) scores_k(const float* __restrict__ a1,
                                                const float* __restrict__ a2) {
    __shared__ float s1[Dd], s2[Dd];
    if (threadIdx.x < Dd)            s1[threadIdx.x]      = a1[threadIdx.x];
    else if (threadIdx.x < 2 * Dd)   s2[threadIdx.x - Dd] = a2[threadIdx.x - Dd];
    __syncthreads();

    const int g  = blockIdx.x * 256 + threadIdx.x;
    const int n  = g >> 2;
    const int hh = g & 3;
    const float* hrow = g_h + (size_t)n * HD + hh * Dd;
    float si = 0.f, sj = 0.f;
    #pragma unroll
    for (int q = 0; q < 16; q++) {
        float4 hv = ((const float4*)hrow)[q];
        si = fmaf(hv.x, s1[4*q+0], si); sj = fmaf(hv.x, s2[4*q+0], sj);
        si = fmaf(hv.y, s1[4*q+1], si); sj = fmaf(hv.y, s2[4*q+1], sj);
        si = fmaf(hv.z, s1[4*q+2], si); sj = fmaf(hv.z, s2[4*q+2], sj);
        si = fmaf(hv.w, s1[4*q+3], si); sj = fmaf(hv.w, s2[4*q+3], sj);
    }
    g_si[g]  = si;                     g_sj[g]  = sj;
    g_eip[g] = __expf(si - 2.f);       g_ejp[g] = __expf(sj - 2.f);
    g_ein[g] = __expf(0.2f*si - 2.f);  g_ejn[g] = __expf(0.2f*sj - 2.f);
}

// ---------------- kernel 2b: pack j-side tables (SoA per 64-chunk) ------------
__global__ void __launch_bounds__(256) tab_pack() {
    const int g  = blockIdx.x * 256 + threadIdx.x;   // 0 .. NN/2*Hh-1
    const int np = g >> 2;
    const int hh = g & 3;
    const int na = 2 * np, nb = 2 * np + 1;
    u32 s  = h2_u32(__floats2half2_rn(g_sj [na*Hh+hh], g_sj [nb*Hh+hh]));
    u32 ep = h2_u32(__floats2half2_rn(g_ejp[na*Hh+hh], g_ejp[nb*Hh+hh]));
    u32 en = h2_u32(__floats2half2_rn(g_ejn[na*Hh+hh], g_ejn[nb*Hh+hh]));
    const int base = (np >> 5) * 384 + hh * 96 + (np & 31);
    g_tab2[base +  0] = s;
    g_tab2[base + 32] = ep;
    g_tab2[base + 64] = en;
}

// ---------------- kernel 3: HMMA aggregation, occupancy 2 ---------------------
// 256 threads (8 warps). grid (128 i-tiles of 32, 2 j-splits) = 256 CTAs.
// Single wS; hS + tab double-buffered via cp.async. Cross-CTA overlap (2/SM)
// replaces the intra-CTA pipeline.
#define HS_STRIDE_B  528                       // 264 halves: 256 data + ones col @512
#define HS_BUF_B     (64 * HS_STRIDE_B)        // 33792
#define WS_HEAD_B    4096                      // 32 rows x 128B
#define OFF_HS   0
#define OFF_WS   (2 * HS_BUF_B)                // 67584 (4 heads x 4096 = 16384)
#define OFF_TAB  (OFF_WS + 4 * WS_HEAD_B)      // 83968
#define TAB_BUF_B 1536
#define SMEM_BYTES_AGG (OFF_TAB + 2 * TAB_BUF_B)   // 87040

__global__ void __launch_bounds__(256, 2) gat_mma(const int* __restrict__ adj) {
    extern __shared__ char sm[];
    const u32 smem_u32 = (u32)__cvta_generic_to_shared(sm);

    const int t     = threadIdx.x;
    const int lane  = t & 31;
    const int wid   = t >> 5;
    const int i0    = blockIdx.x * TIA;
    const int split = blockIdx.y;
    const int jbase0 = split * JPER;

    // Phase-A ids: 1 i-row per thread, 4 j-pairs (grp)
    const int iA  = t >> 3;                    // 0..31
    const int grp = t & 7;                     // 0..7

    // MMA warp tiling: 1 i-group (32 rows) x 8 col-groups (32 cols)
    const int cw8  = wid;                      // 0..7
    const int ncol = cw8 * 32;                 // halves
    const int headA = cw8 >> 1;
    const bool doZ  = (cw8 & 1) == 0;
    const int rowL = (lane & 7) + (lane & 8);
    const int colL = (lane >> 4) << 3;

    // i-side constants: rsi dup-half2 and packed (eip,ein) per head
    u32 rsi2[4], rpn[4];
    #pragma unroll
    for (int h = 0; h < 4; h++) {
        const size_t gix = (size_t)(i0 + iA) * Hh + h;
        rsi2[h] = h2_u32(__float2half2_rn(g_si[gix]));
        rpn[h]  = h2_u32(__halves2half2(__float2half(g_eip[gix]),
                                        __float2half(g_ein[gix])));
    }
    const __half2 hz = __float2half2_rn(0.f);

    float acc[8][4];
    #pragma unroll
    for (int q = 0; q < 8; q++)
        #pragma unroll
        for (int r = 0; r < 4; r++) acc[q][r] = 0.f;
    float zacc[2][4];
    #pragma unroll
    for (int m = 0; m < 2; m++)
        #pragma unroll
        for (int r = 0; r < 4; r++) zacc[m][r] = 0.f;

    // ---- staging helpers (cp.async) ----
    auto stage_h = [&](int c) {                // hS(c) -> buffer c&1
        const u32 hb = smem_u32 + OFF_HS + (u32)(c & 1) * HS_BUF_B;
        const char* gsrc = (const char*)(g_hh + (size_t)(jbase0 + c * JC) * HD);
        #pragma unroll
        for (int r = 0; r < 8; r++) {
            int v = r * 256 + t;               // 0..2047 int4
            int j = v >> 5, c16 = v & 31;
            cp_async16(hb + j * HS_STRIDE_B + c16 * 16, gsrc + (size_t)v * 16);
        }
    };
    auto stage_tab = [&](int c) {              // tab(c) -> buffer c&1
        if (t < 96) {
            const u32 tb = smem_u32 + OFF_TAB + (u32)(c & 1) * TAB_BUF_B;
            const char* tsrc = (const char*)(g_tab2 + (size_t)((jbase0 + c * JC) >> 6) * 384);
            cp_async16(tb + t * 16, tsrc + t * 16);
        }
    };
    auto adj_ld = [&](int c, int4& av0, int4& av1) {
        const int* ar = adj + (size_t)(i0 + iA) * NN + jbase0 + c * JC + grp * 8;
        av0 = ((const int4*)ar)[0];
        av1 = ((const int4*)ar)[1];
    };
    // ---- Phase A: compute w(c) -> single wS ----
    auto phaseA = [&](int c, int4 av0, int4 av1) {
        const u32 tb = smem_u32 + OFF_TAB + (u32)(c & 1) * TAB_BUF_B;
        const int avv[8] = {av0.x, av0.y, av0.z, av0.w, av1.x, av1.y, av1.z, av1.w};
        u32 em[4];
        #pragma unroll
        for (int p = 0; p < 4; p++)
            em[p] = h2_u32(__floats2half2_rn((float)avv[2*p], (float)avv[2*p+1]));
        const u32 wsbase = smem_u32 + OFF_WS
                         + (u32)iA * 128 + (((u32)grp * 16) ^ (((u32)(iA & 7)) << 4));
        #pragma unroll
        for (int h = 0; h < 4; h++) {
            const u32 tadr = tb + (u32)(h * 96 + grp * 4) * 4;
            int4 ts = lds128(tadr);
            int4 tp = lds128(tadr + 128);
            int4 tn = lds128(tadr + 256);
            const u32 tsv[4] = {(u32)ts.x,(u32)ts.y,(u32)ts.z,(u32)ts.w};
            const u32 tpv[4] = {(u32)tp.x,(u32)tp.y,(u32)tp.z,(u32)tp.w};
            const u32 tnv[4] = {(u32)tn.x,(u32)tn.y,(u32)tn.z,(u32)tn.w};
            __half2 rp   = u32_h2(rpn[h]);
            __half2 rep2 = __low2half2(rp);
            __half2 ren2 = __high2half2(rp);
            u32 wv[4];
            #pragma unroll
            for (int p = 0; p < 4; p++) {
                __half2 t2 = __hadd2(u32_h2(rsi2[h]), u32_h2(tsv[p]));
                __half2 p2 = __hmul2(rep2, u32_h2(tpv[p]));
                __half2 n2 = __hmul2(ren2, u32_h2(tnv[p]));
                __half2 m2 = __hge2(t2, hz);
                __half2 w2 = __hfma2(m2, __hsub2(p2, n2), n2);
                wv[p] = h2_u32(__hmul2(w2, u32_h2(em[p])));
            }
            sts128(wsbase + (u32)h * WS_HEAD_B, wv[0], wv[1], wv[2], wv[3]);
        }
    };

    // ---- prologue ----
    if (t < 128) {                              // ones columns, both hS buffers
        int buf = t >> 6, j = t & 63;
        *(int4*)(sm + OFF_HS + buf * HS_BUF_B + j * HS_STRIDE_B + 512) =
            make_int4(0x3C00, 0, 0, 0);
    }
    stage_h(0); stage_tab(0); cp_commit();
    int4 av0, av1;
    adj_ld(0, av0, av1);
    cp_wait0();
    __syncthreads();

    // ---- main loop ----
    for (int c = 0; c < NCHUNK; c++) {
        // stage next chunk (buffer (c+1)&1 is free: last read at MMA(c-1))
        if (c + 1 < NCHUNK) { stage_h(c + 1); stage_tab(c + 1); cp_commit(); }
        // prefetch next adj into fresh regs
        int4 nv0, nv1;
        if (c + 1 < NCHUNK) adj_ld(c + 1, nv0, nv1);

        phaseA(c, av0, av1);
        __syncthreads();                       // wS published

        // Phase B: MMA(c)
        const u32 hbase = smem_u32 + OFF_HS + (u32)(c & 1) * HS_BUF_B;
        const u32 wsrd  = smem_u32 + OFF_WS + (u32)(headA * WS_HEAD_B);
        #pragma unroll
        for (int ks = 0; ks < 4; ks++) {
            u32 A0[4], A1[4];
            {
                const int r0 = rowL, r1 = 16 + rowL;
                const u32 cb = (u32)(ks * 32) + ((u32)(lane >> 4) << 4);
                u32 a0a = wsrd + (u32)r0 * 128 + (cb ^ (((u32)(r0 & 7)) << 4));
                u32 a1a = wsrd + (u32)r1 * 128 + (cb ^ (((u32)(r1 & 7)) << 4));
                ldsm_x4(A0[0], A0[1], A0[2], A0[3], a0a);
                ldsm_x4(A1[0], A1[1], A1[2], A1[3], a1a);
            }
            if (doZ) {
                u32 bo0, bo1;
                ldsm_x2_t(bo0, bo1, hbase + (u32)(ks * 16 + rowL) * HS_STRIDE_B + 512);
                mma16816(zacc[0], A0[0], A0[1], A0[2], A0[3], bo0, bo1);
                mma16816(zacc[1], A1[0], A1[1], A1[2], A1[3], bo0, bo1);
            }
            #pragma unroll
            for (int p = 0; p < 2; p++) {
                u32 b0, b1, b2, b3;
                u32 ba = hbase + (u32)(ks * 16 + rowL) * HS_STRIDE_B
                       + (u32)(ncol + p * 16 + colL) * 2;
                ldsm_x4_t(b0, b1, b2, b3, ba);
                mma16816(acc[p*2 + 0], A0[0], A0[1], A0[2], A0[3], b0, b1);
                mma16816(acc[p*2 + 1], A0[0], A0[1], A0[2], A0[3], b2, b3);
                mma16816(acc[4 + p*2 + 0], A1[0], A1[1], A1[2], A1[3], b0, b1);
                mma16816(acc[4 + p*2 + 1], A1[0], A1[1], A1[2], A1[3], b2, b3);
            }
        }
        av0 = nv0; av1 = nv1;

        cp_wait0();           // next hS/tab landed
        __syncthreads();      // MMA(c) done -> wS free; staging visible
    }

    // ---- writeback partials ----
    {
        float* base = g_part + (size_t)split * NN * HD;
        const int cc = (lane & 3) * 2;
        #pragma unroll
        for (int m = 0; m < 2; m++) {
            const int r0 = i0 + m * 16 + (lane >> 2);
            #pragma unroll
            for (int n = 0; n < 4; n++) {
                const int col = ncol + n * 8 + cc;
                *(float2*)&base[(size_t)(r0    ) * HD + col] =
                    make_float2(acc[m*4+n][0], acc[m*4+n][1]);
                *(float2*)&base[(size_t)(r0 + 8) * HD + col] =
                    make_float2(acc[m*4+n][2], acc[m*4+n][3]);
            }
        }
    }
    if (doZ && (lane & 3) == 0) {
        float* zb = g_Z + (size_t)split * NN * Hh;
        #pragma unroll
        for (int m = 0; m < 2; m++) {
            const int r0 = i0 + m * 16 + (lane >> 2);
            zb[(size_t)(r0    ) * Hh + headA] = zacc[m][0];
            zb[(size_t)(r0 + 8) * Hh + headA] = zacc[m][2];
        }
    }
}

// ---------------- kernel 4: combine splits + normalize -----------------------
__global__ void __launch_bounds__(256) epilogue_k(float* __restrict__ out) {
    int e = blockIdx.x * 256 + threadIdx.x;
    float p = g_part[e] + g_part[(size_t)NN * HD + e];
    int i = e >> 8;
    int head = (e & 255) >> 6;
    float z = g_Z[i * Hh + head] + g_Z[(size_t)NN * Hh + i * Hh + head];
    out[e] = p / z;
}

// ---------------- launch ------------------------------------------------------
extern "C" void kernel_launch(void* const* d_in, const int* in_sizes, int n_in,
                              void* d_out, int out_size) {
    const float* x   = (const float*)d_in[0];
    const int*   adj = (const int*)  d_in[1];
    const float* W   = (const float*)d_in[2];
    const float* a1  = (const float*)d_in[3];
    const float* a2  = (const float*)d_in[4];
    float* out = (float*)d_out;

    cudaFuncSetAttribute(gat_mma, cudaFuncAttributeMaxDynamicSharedMemorySize,
                         SMEM_BYTES_AGG);

    gemm_xw  <<<dim3(HD/64, NN/64), 256>>>(x, W);
    scores_k <<<(NN*Hh)/256, 256>>>(a1, a2);
    tab_pack <<<(NN/2*Hh)/256, 256>>>();
    gat_mma  <<<dim3(NN/TIA, JSPLIT), 256, SMEM_BYTES_AGG>>>(adj);
    epilogue_k<<<(NN*HD)/256, 256>>>(out);
}